// round 14
// baseline (speedup 1.0000x reference)
#include <cuda_runtime.h>
#include <cuda_bf16.h>
#include <math.h>
#include <cstdint>

#define BATCH  2
#define SEQ    2048
#define HIDDEN 1024
#define NHEAD  16
#define HD     64
#define MROWS  (BATCH*SEQ)   // 4096

__device__ __forceinline__ float tanha(float x) {
    asm("tanh.approx.f32 %0,%0;" : "+f"(x)); return x;
}
__device__ __forceinline__ uint32_t smem_u32(const void* p) {
    uint32_t a;
    asm("{ .reg .u64 t; cvta.to.shared.u64 t, %1; cvt.u32.u64 %0, t; }"
        : "=r"(a) : "l"(p));
    return a;
}
__device__ __forceinline__ void ldsm4(uint32_t* r, uint32_t addr) {
    asm volatile("ldmatrix.sync.aligned.m8n8.x4.shared.b16 {%0,%1,%2,%3}, [%4];"
                 : "=r"(r[0]), "=r"(r[1]), "=r"(r[2]), "=r"(r[3]) : "r"(addr));
}
__device__ __forceinline__ void mma16816(float* c, const uint32_t* a,
                                         const uint32_t* b) {
    asm volatile(
        "mma.sync.aligned.m16n8k16.row.col.f32.bf16.bf16.f32 "
        "{%0,%1,%2,%3}, {%4,%5,%6,%7}, {%8,%9}, {%0,%1,%2,%3};"
        : "+f"(c[0]), "+f"(c[1]), "+f"(c[2]), "+f"(c[3])
        : "r"(a[0]), "r"(a[1]), "r"(a[2]), "r"(a[3]), "r"(b[0]), "r"(b[1]));
}
__device__ __forceinline__ void cpa16(uint32_t dst, const void* src) {
    asm volatile("cp.async.cg.shared.global [%0], [%1], 16;"
                 :: "r"(dst), "l"(src));
}
#define CP_COMMIT() asm volatile("cp.async.commit_group;" ::: "memory")
#define CP_WAIT0()  asm volatile("cp.async.wait_group 0;" ::: "memory")

// packed split: h = bf16x2(lo=x, hi=y); residuals handled by caller
__device__ __forceinline__ uint32_t cvt2bf(float lo, float hi) {
    uint32_t r;
    asm("cvt.rn.bf16x2.f32 %0,%1,%2;" : "=r"(r) : "f"(hi), "f"(lo));
    return r;
}
// softcap + fixed-shift exp: p = exp(30*tanh((s/8 + ab)/30) - 30)
__device__ __forceinline__ float softcap_p(float s, float ab) {
    float t = fmaf(s, 0.125f, ab);
    float th = tanha(t * (1.f / 30.f));
    return __expf(fmaf(30.f, th, -30.f));
}

// ---- scratch (device globals; ONLY referenced from device code) ------------
__device__ __align__(16) __nv_bfloat16 g_Xh[MROWS*HIDDEN];
__device__ __align__(16) __nv_bfloat16 g_Xl[MROWS*HIDDEN];
__device__ __align__(16) __nv_bfloat16 g_Ch[MROWS*HIDDEN];
__device__ __align__(16) __nv_bfloat16 g_Cl[MROWS*HIDDEN];
__device__ __align__(16) __nv_bfloat16 g_Wh[4*HIDDEN*HIDDEN];  // [z][n][k]
__device__ __align__(16) __nv_bfloat16 g_Wl[4*HIDDEN*HIDDEN];
__device__ __align__(16) __nv_bfloat16 g_Qh[BATCH*NHEAD*SEQ*HD]; // [b,h,s,d]
__device__ __align__(16) __nv_bfloat16 g_Ql[BATCH*NHEAD*SEQ*HD];
__device__ __align__(16) __nv_bfloat16 g_Kh[BATCH*NHEAD*SEQ*HD];
__device__ __align__(16) __nv_bfloat16 g_Kl[BATCH*NHEAD*SEQ*HD];
__device__ __align__(16) __nv_bfloat16 g_Vth[BATCH*NHEAD*HD*SEQ]; // [b,h,d,s]
__device__ __align__(16) __nv_bfloat16 g_Vtl[BATCH*NHEAD*HD*SEQ];

// ---------------------------------------------------------------------------
// Split fp32 X -> bf16 hi/lo.
// ---------------------------------------------------------------------------
__global__ __launch_bounds__(256)
void conv_split(const float* __restrict__ src)
{
    size_t i = ((size_t)blockIdx.x * 256 + threadIdx.x) * 4;
    float4 v = *(const float4*)(src + i);
    __nv_bfloat16 h0 = __float2bfloat16(v.x), h1 = __float2bfloat16(v.y);
    __nv_bfloat16 h2 = __float2bfloat16(v.z), h3 = __float2bfloat16(v.w);
    __nv_bfloat16 l0 = __float2bfloat16(v.x - __bfloat162float(h0));
    __nv_bfloat16 l1 = __float2bfloat16(v.y - __bfloat162float(h1));
    __nv_bfloat16 l2 = __float2bfloat16(v.z - __bfloat162float(h2));
    __nv_bfloat16 l3 = __float2bfloat16(v.w - __bfloat162float(h3));
    __nv_bfloat162* hp = (__nv_bfloat162*)(g_Xh + i);
    __nv_bfloat162* lp = (__nv_bfloat162*)(g_Xl + i);
    hp[0] = __nv_bfloat162(h0, h1); hp[1] = __nv_bfloat162(h2, h3);
    lp[0] = __nv_bfloat162(l0, l1); lp[1] = __nv_bfloat162(l2, l3);
}

// ---------------------------------------------------------------------------
// Transpose + split the 4 weight matrices: W[k][n] fp32 -> Wh/Wl[z][n][k] bf16.
// ---------------------------------------------------------------------------
__global__ __launch_bounds__(256)
void conv_wT(const float* __restrict__ W0, const float* __restrict__ W1,
             const float* __restrict__ W2, const float* __restrict__ W3)
{
    __shared__ float t[32][33];
    const int z = blockIdx.z;
    const float* W = (z == 0) ? W0 : (z == 1) ? W1 : (z == 2) ? W2 : W3;
    __nv_bfloat16* Ho = g_Wh + (size_t)z * HIDDEN * HIDDEN;
    __nv_bfloat16* Lo = g_Wl + (size_t)z * HIDDEN * HIDDEN;
    const int k0 = blockIdx.x * 32, n0 = blockIdx.y * 32;
    const int tx = threadIdx.x & 31, ty = threadIdx.x >> 5;  // 32x8
#pragma unroll
    for (int r = 0; r < 4; r++)
        t[ty + r * 8][tx] = W[(size_t)(k0 + ty + r * 8) * HIDDEN + n0 + tx];
    __syncthreads();
#pragma unroll
    for (int r = 0; r < 4; r++) {
        int nr = ty + r * 8;
        float x = t[tx][nr];
        __nv_bfloat16 h = __float2bfloat16(x);
        Ho[(size_t)(n0 + nr) * HIDDEN + k0 + tx] = h;
        Lo[(size_t)(n0 + nr) * HIDDEN + k0 + tx] =
            __float2bfloat16(x - __bfloat162float(h));
    }
}

// ---------------------------------------------------------------------------
// Fused QKV GEMM: one CTA computes Q, K, V tiles for its (m,n) block.
// 512 thr = 16 warps (4m x 4n), warp tile 32x32 per z, CTA tile 128x128,
// K-chunk 32, cp.async 2-stage. A (X hi/lo) loaded+LDSM'd ONCE per chunk,
// reused for all 3 weight slabs: L2 A-traffic /3, LDSM:MMA = 1:4.5.
// ---------------------------------------------------------------------------
#define GLDA 40
#define GT 10240                       // bytes per tile (128 rows * 40 * 2)
#define QSTG (8*GT)                    // Ah,Al,Bh0,Bl0,Bh1,Bl1,Bh2,Bl2
#define SMEM_QKV (2*QSTG)              // 163840

__global__ __launch_bounds__(512)
void gemm_qkv()
{
    extern __shared__ __align__(16) char gsm[];
    const uint32_t sb = smem_u32(gsm);

    const int tid = threadIdx.x;
    const int wid = tid >> 5, lane = tid & 31;
    const int wm = wid >> 2, wn = wid & 3;           // 4x4 warp grid
    const int bn = blockIdx.x * 128, bm = blockIdx.y * 128;

    const int lr = tid >> 2;        // load row (0..127)
    const int lku = tid & 3;        // 16B k-unit (0..3)

    float acc[3][2][4][4];
#pragma unroll
    for (int z = 0; z < 3; z++)
#pragma unroll
        for (int i = 0; i < 2; i++)
#pragma unroll
            for (int j = 0; j < 4; j++)
#pragma unroll
                for (int q = 0; q < 4; q++) acc[z][i][j][q] = 0.f;

    auto load_chunk = [&](int c) {
        const int k0 = c * 32;
        const uint32_t bb = sb + (c & 1) * QSTG;
        const size_t goA = (size_t)(bm + lr) * HIDDEN + k0 + lku * 8;
        const size_t goB = (size_t)(bn + lr) * HIDDEN + k0 + lku * 8;
        const uint32_t so = (lr * GLDA + lku * 8) * 2;
        cpa16(bb + 0 * GT + so, g_Xh + goA);
        cpa16(bb + 1 * GT + so, g_Xl + goA);
#pragma unroll
        for (int z = 0; z < 3; z++) {
            cpa16(bb + (2 + 2 * z) * GT + so,
                  g_Wh + (size_t)z * HIDDEN * HIDDEN + goB);
            cpa16(bb + (3 + 2 * z) * GT + so,
                  g_Wl + (size_t)z * HIDDEN * HIDDEN + goB);
        }
    };

    load_chunk(0);
    CP_COMMIT();

    const int lrow = lane & 15;
    const int lcol = (lane >> 4) * 8;

    for (int c = 0; c < 32; c++) {
        CP_WAIT0();
        __syncthreads();   // data(c) arrived AND all warps done reading (c-1)
        if (c + 1 < 32) { load_chunk(c + 1); CP_COMMIT(); }

        const uint32_t bb = sb + (c & 1) * QSTG;
#pragma unroll
        for (int kt = 0; kt < 2; kt++) {
            const int kc = kt * 16 + lcol;
            uint32_t ah[2][4], al[2][4];
#pragma unroll
            for (int i = 0; i < 2; i++) {
                const int row = wm * 32 + i * 16 + lrow;
                const uint32_t ao = (row * GLDA + kc) * 2;
                ldsm4(ah[i], bb + 0 * GT + ao);
                ldsm4(al[i], bb + 1 * GT + ao);
            }
#pragma unroll
            for (int z = 0; z < 3; z++) {
                uint32_t bh[4][2], bl[4][2];
#pragma unroll
                for (int jj = 0; jj < 2; jj++) {
                    const int row = wn * 32 + jj * 16 + lrow;
                    const uint32_t bo = (row * GLDA + kc) * 2;
                    uint32_t t4[4];
                    ldsm4(t4, bb + (2 + 2 * z) * GT + bo);
                    bh[2*jj][0]   = t4[0]; bh[2*jj][1]   = t4[2];
                    bh[2*jj+1][0] = t4[1]; bh[2*jj+1][1] = t4[3];
                    ldsm4(t4, bb + (3 + 2 * z) * GT + bo);
                    bl[2*jj][0]   = t4[0]; bl[2*jj][1]   = t4[2];
                    bl[2*jj+1][0] = t4[1]; bl[2*jj+1][1] = t4[3];
                }
#pragma unroll
                for (int i = 0; i < 2; i++)
#pragma unroll
                    for (int j = 0; j < 4; j++) {
                        mma16816(acc[z][i][j], ah[i], bh[j]);
                        mma16816(acc[z][i][j], ah[i], bl[j]);
                        mma16816(acc[z][i][j], al[i], bh[j]);
                    }
            }
        }
    }

    // ---- epilogue: Q,K -> split [b,h,s,d]; V -> split transposed [b,h,d,s] --
    const int g2 = lane >> 2, q2 = (lane & 3) * 2;
#pragma unroll
    for (int z = 0; z < 3; z++) {
#pragma unroll
        for (int i = 0; i < 2; i++) {
            const int row0 = bm + wm * 32 + i * 16 + g2;
#pragma unroll
            for (int j = 0; j < 4; j++) {
                const int col = bn + wn * 32 + j * 8 + q2;
                const int h = col >> 6, d = col & 63;
                if (z < 2) {
                    __nv_bfloat16* Hm = z ? g_Kh : g_Qh;
                    __nv_bfloat16* Lm = z ? g_Kl : g_Ql;
#pragma unroll
                    for (int rr = 0; rr < 2; rr++) {
                        const int row = row0 + rr * 8;
                        const int bb = row >> 11, ss = row & (SEQ - 1);
                        const size_t o =
                            (((size_t)(bb * NHEAD + h) * SEQ) + ss) * HD + d;
                        const float x0 = acc[z][i][j][rr * 2];
                        const float x1 = acc[z][i][j][rr * 2 + 1];
                        const uint32_t hh = cvt2bf(x0, x1);
                        *(uint32_t*)&Hm[o] = hh;
                        *(uint32_t*)&Lm[o] = cvt2bf(
                            x0 - __uint_as_float(hh << 16),
                            x1 - __uint_as_float(hh & 0xFFFF0000u));
                    }
                } else {
#pragma unroll
                    for (int rr = 0; rr < 2; rr++) {
                        const int row = row0 + rr * 8;
                        const int bb = row >> 11, ss = row & (SEQ - 1);
                        const size_t base = (size_t)(bb * NHEAD + h) * HD;
#pragma unroll
                        for (int cc = 0; cc < 2; cc++) {
                            const float x = acc[z][i][j][rr * 2 + cc];
                            __nv_bfloat16 hh = __float2bfloat16(x);
                            const size_t o = (base + d + cc) * SEQ + ss;
                            g_Vth[o] = hh;
                            g_Vtl[o] =
                                __float2bfloat16(x - __bfloat162float(hh));
                        }
                    }
                }
            }
        }
    }
}

// ---------------------------------------------------------------------------
// Output-projection GEMM (R12 v2, unchanged): 512 thr, 16 warps, 128x128,
// cp.async 2-stage, ldmatrix, 3-pass split. ctx(hi/lo) @ Wo + bias -> out.
// ---------------------------------------------------------------------------
#define GTILE_B (128*GLDA*2)
#define GBUF_B  (4*GTILE_B)
#define SMEM_GEMM (2*GBUF_B)

__global__ __launch_bounds__(512)
void gemm_out(const float* __restrict__ bias, float* __restrict__ Cout)
{
    extern __shared__ __align__(16) char gsm[];
    const uint32_t sb = smem_u32(gsm);

    const int tid = threadIdx.x;
    const int wid = tid >> 5, lane = tid & 31;
    const int wm = wid >> 2, wn = wid & 3;
    const int bn = blockIdx.x * 128, bm = blockIdx.y * 128;

    const __nv_bfloat16* Bhg = g_Wh + (size_t)3 * HIDDEN * HIDDEN;
    const __nv_bfloat16* Blg = g_Wl + (size_t)3 * HIDDEN * HIDDEN;

    const int lr = tid >> 2;
    const int lku = tid & 3;

    float acc[2][4][4];
#pragma unroll
    for (int i = 0; i < 2; i++)
#pragma unroll
        for (int j = 0; j < 4; j++)
#pragma unroll
            for (int q = 0; q < 4; q++) acc[i][j][q] = 0.f;

    auto load_chunk = [&](int c) {
        const int k0 = c * 32;
        const uint32_t bb = sb + (c & 1) * GBUF_B;
        const size_t goA = (size_t)(bm + lr) * HIDDEN + k0 + lku * 8;
        const size_t goB = (size_t)(bn + lr) * HIDDEN + k0 + lku * 8;
        const uint32_t so = (lr * GLDA + lku * 8) * 2;
        cpa16(bb + 0 * GTILE_B + so, g_Ch + goA);
        cpa16(bb + 1 * GTILE_B + so, g_Cl + goA);
        cpa16(bb + 2 * GTILE_B + so, Bhg + goB);
        cpa16(bb + 3 * GTILE_B + so, Blg + goB);
    };

    load_chunk(0);
    CP_COMMIT();

    const int lrow = lane & 15;
    const int lcol = (lane >> 4) * 8;

    for (int c = 0; c < 32; c++) {
        CP_WAIT0();
        __syncthreads();
        if (c + 1 < 32) { load_chunk(c + 1); CP_COMMIT(); }

        const uint32_t bb = sb + (c & 1) * GBUF_B;
#pragma unroll
        for (int kt = 0; kt < 2; kt++) {
            const int kc = kt * 16 + lcol;
            uint32_t ah[2][4], al[2][4];
#pragma unroll
            for (int i = 0; i < 2; i++) {
                const int row = wm * 32 + i * 16 + lrow;
                const uint32_t ao = (row * GLDA + kc) * 2;
                ldsm4(ah[i], bb + 0 * GTILE_B + ao);
                ldsm4(al[i], bb + 1 * GTILE_B + ao);
            }
            uint32_t bh[4][2], bl[4][2];
#pragma unroll
            for (int jj = 0; jj < 2; jj++) {
                const int row = wn * 32 + jj * 16 + lrow;
                const uint32_t bo = (row * GLDA + kc) * 2;
                uint32_t t4[4];
                ldsm4(t4, bb + 2 * GTILE_B + bo);
                bh[2*jj][0]   = t4[0]; bh[2*jj][1]   = t4[2];
                bh[2*jj+1][0] = t4[1]; bh[2*jj+1][1] = t4[3];
                ldsm4(t4, bb + 3 * GTILE_B + bo);
                bl[2*jj][0]   = t4[0]; bl[2*jj][1]   = t4[2];
                bl[2*jj+1][0] = t4[1]; bl[2*jj+1][1] = t4[3];
            }
#pragma unroll
            for (int i = 0; i < 2; i++)
#pragma unroll
                for (int j = 0; j < 4; j++) {
                    mma16816(acc[i][j], ah[i], bh[j]);
                    mma16816(acc[i][j], ah[i], bl[j]);
                    mma16816(acc[i][j], al[i], bh[j]);
                }
        }
    }

    const int g2 = lane >> 2, q2 = (lane & 3) * 2;
#pragma unroll
    for (int i = 0; i < 2; i++) {
        const int row0 = bm + wm * 32 + i * 16 + g2;
#pragma unroll
        for (int j = 0; j < 4; j++) {
            const int col = bn + wn * 32 + j * 8 + q2;
            const float2 bb2 = *(const float2*)(bias + col);
            float* p0 = Cout + (size_t)row0 * HIDDEN + col;
            *(float2*)p0 = make_float2(acc[i][j][0] + bb2.x,
                                       acc[i][j][1] + bb2.y);
            float* p1 = Cout + (size_t)(row0 + 8) * HIDDEN + col;
            *(float2*)p1 = make_float2(acc[i][j][2] + bb2.x,
                                       acc[i][j][3] + bb2.y);
        }
    }
}

// ---------------------------------------------------------------------------
// HMMA flash attention v5 (unchanged from R12): fixed softcap shift, softmax
// fused into PV per k-chunk, packed-cvt P splitting, single sync per kt,
// descending-qt order.
// ---------------------------------------------------------------------------
#define ALD 72
#define ATB (64*ALD*2)
#define A_KH 0
#define A_KL ATB
#define A_VH (2*ATB)
#define A_VL (3*ATB)
#define A_MSK (4*ATB)
#define ASTG (4*ATB + 256)
#define SMEM_ATTN (2*ASTG)

__global__ __launch_bounds__(128, 3)
void attn_k(const int* __restrict__ amask)
{
    extern __shared__ __align__(16) char smb[];
    const uint32_t sb = smem_u32(smb);

    const int qt = gridDim.x - 1 - blockIdx.x;   // big tiles first (LPT)
    const int h = blockIdx.y, b = blockIdx.z;
    const int tid = threadIdx.x;
    const int wid = tid >> 5, lane = tid & 31;
    const int fr = lane >> 2, fc = (lane & 3) * 2;
    const int lrow = lane & 15, lcol = (lane >> 4) * 8;
    const float slope = exp2f(-0.5f * (float)(h + 1));
    const float sl8 = slope * 0.125f;

    const size_t hb = (size_t)(b * NHEAD + h);
    const __nv_bfloat16* Khg0 = g_Kh + hb * SEQ * HD;
    const __nv_bfloat16* Klg0 = g_Kl + hb * SEQ * HD;
    const __nv_bfloat16* Vhg0 = g_Vth + hb * HD * SEQ;
    const __nv_bfloat16* Vlg0 = g_Vtl + hb * HD * SEQ;
    const int* mrow = amask + b * SEQ;

    const int m0 = wid * 16;

    // ---- stage Q through stage-0 K area, ldsm into registers ----
    {
        const __nv_bfloat16* Qhg = g_Qh + (hb * SEQ + qt * 64) * HD;
        const __nv_bfloat16* Qlg = g_Ql + (hb * SEQ + qt * 64) * HD;
        __nv_bfloat16* tQh = (__nv_bfloat16*)(smb + A_KH);
        __nv_bfloat16* tQl = (__nv_bfloat16*)(smb + A_KL);
#pragma unroll
        for (int it = 0; it < 4; it++) {
            const int i = tid + it * 128;
            const int row = i >> 3, u = (i & 7) * 8;
            *(uint4*)&tQh[row * ALD + u] = *(const uint4*)(Qhg + row * HD + u);
            *(uint4*)&tQl[row * ALD + u] = *(const uint4*)(Qlg + row * HD + u);
        }
    }
    __syncthreads();
    uint32_t qh[4][4], ql[4][4];
#pragma unroll
    for (int kk = 0; kk < 4; kk++) {
        const uint32_t ao = ((m0 + lrow) * ALD + kk * 16 + lcol) * 2;
        ldsm4(qh[kk], sb + A_KH + ao);
        ldsm4(ql[kk], sb + A_KL + ao);
    }
    __syncthreads();

    auto prefetch = [&](int kt) {
        const uint32_t st = sb + (kt & 1) * ASTG;
        const __nv_bfloat16* Khg = Khg0 + (size_t)kt * 64 * HD;
        const __nv_bfloat16* Klg = Klg0 + (size_t)kt * 64 * HD;
        const __nv_bfloat16* Vhg = Vhg0 + kt * 64;
        const __nv_bfloat16* Vlg = Vlg0 + kt * 64;
#pragma unroll
        for (int it = 0; it < 4; it++) {
            const int i = tid + it * 128;
            const int row = i >> 3, u = (i & 7) * 8;
            const uint32_t so = (row * ALD + u) * 2;
            cpa16(st + A_KH + so, Khg + row * HD + u);
            cpa16(st + A_KL + so, Klg + row * HD + u);
            cpa16(st + A_VH + so, Vhg + (size_t)row * SEQ + u);
            cpa16(st + A_VL + so, Vlg + (size_t)row * SEQ + u);
        }
        if (tid < 16) cpa16(st + A_MSK + tid * 16, mrow + kt * 64 + tid * 4);
    };

    float l[2] = {0.f, 0.f};
    float accO[8][4];
#pragma unroll
    for (int j = 0; j < 8; j++)
#pragma unroll
        for (int q = 0; q < 4; q++) accO[j][q] = 0.f;

    const int qi0 = qt * 64 + m0 + fr;

    prefetch(0);
    CP_COMMIT();

    for (int kt = 0; kt <= qt; kt++) {
        CP_WAIT0();
        __syncthreads();   // stage(kt) arrived AND all warps done with kt-1
        if (kt < qt) { prefetch(kt + 1); CP_COMMIT(); }

        const uint32_t st = sb + (kt & 1) * ASTG;
        const int* padm = (const int*)(smb + (kt & 1) * ASTG + A_MSK);

        // ---- S = Q K^T (3-pass) ----
        float sacc[8][4];
#pragma unroll
        for (int j = 0; j < 8; j++)
#pragma unroll
            for (int q = 0; q < 4; q++) sacc[j][q] = 0.f;

#pragma unroll
        for (int kk = 0; kk < 4; kk++) {
            const uint32_t kc2 = (kk * 16 + lcol) * 2;
#pragma unroll
            for (int jj = 0; jj < 4; jj++) {
                const uint32_t bo = (uint32_t)((jj * 16 + lrow) * ALD * 2) + kc2;
                uint32_t th[4], tl[4];
                ldsm4(th, st + A_KH + bo);
                ldsm4(tl, st + A_KL + bo);
                uint32_t b0h[2] = { th[0], th[2] }, b1h[2] = { th[1], th[3] };
                uint32_t b0l[2] = { tl[0], tl[2] }, b1l[2] = { tl[1], tl[3] };
                mma16816(sacc[2*jj],   qh[kk], b0h);
                mma16816(sacc[2*jj],   qh[kk], b0l);
                mma16816(sacc[2*jj],   ql[kk], b0h);
                mma16816(sacc[2*jj+1], qh[kk], b1h);
                mma16816(sacc[2*jj+1], qh[kk], b1l);
                mma16816(sacc[2*jj+1], ql[kk], b1h);
            }
        }

        // ---- fused softcap+fixed-shift softmax -> PV per k-chunk ----
        const bool diag = (kt == qt);
        const int pv0 = padm[2 * lane], pv1 = padm[2 * lane + 1];
        const bool allok = __all_sync(0xffffffffu, pv0 && pv1);
        const bool slow = diag || !allok;
        const float aK = sl8 * (float)(64 * (kt - qt) + fc - m0 - fr);

#pragma unroll
        for (int kk = 0; kk < 4; kk++) {
            uint32_t pa_h[4], pa_l[4];
#pragma unroll
            for (int jj2 = 0; jj2 < 2; jj2++) {
                const int j = 2 * kk + jj2;
                const float abj = fmaf(sl8, (float)(8 * j), aK);
                float p00 = softcap_p(sacc[j][0], abj);
                float p01 = softcap_p(sacc[j][1], abj + sl8);
                float p10 = softcap_p(sacc[j][2], abj - 8.f * sl8);
                float p11 = softcap_p(sacc[j][3], abj - 7.f * sl8);
                if (slow) {
                    const int kc0 = kt * 64 + j * 8 + fc;
                    const int pm0 = padm[j * 8 + fc];
                    const int pm1 = padm[j * 8 + fc + 1];
                    const int qiA = qi0, qiB = qi0 + 8;
                    if (pm0 == 0 || (diag && kc0     > qiA)) p00 = 0.f;
                    if (pm1 == 0 || (diag && kc0 + 1 > qiA)) p01 = 0.f;
                    if (pm0 == 0 || (diag && kc0     > qiB)) p10 = 0.f;
                    if (pm1 == 0 || (diag && kc0 + 1 > qiB)) p11 = 0.f;
                }
                l[0] += p00 + p01;
                l[1] += p10 + p11;
                const uint32_t h0 = cvt2bf(p00, p01);
                const uint32_t h1 = cvt2bf(p10, p11);
                pa_h[jj2 * 2]     = h0;
                pa_h[jj2 * 2 + 1] = h1;
                pa_l[jj2 * 2]     = cvt2bf(
                    p00 - __uint_as_float(h0 << 16),
                    p01 - __uint_as_float(h0 & 0xFFFF0000u));
                pa_l[jj2 * 2 + 1] = cvt2bf(
                    p10 - __uint_as_float(h1 << 16),
                    p11 - __uint_as_float(h1 & 0xFFFF0000u));
            }
            const uint32_t kc2 = (kk * 16 + lcol) * 2;
#pragma unroll
            for (int jj = 0; jj < 4; jj++) {
                const uint32_t bo = (uint32_t)((jj * 16 + lrow) * ALD * 2) + kc2;
                uint32_t th[4], tl[4];
                ldsm4(th, st + A_VH + bo);
                ldsm4(tl, st + A_VL + bo);
                uint32_t b0h[2] = { th[0], th[2] }, b1h[2] = { th[1], th[3] };
                uint32_t b0l[2] = { tl[0], tl[2] }, b1l[2] = { tl[1], tl[3] };
                mma16816(accO[2*jj],   pa_h, b0h);
                mma16816(accO[2*jj],   pa_h, b0l);
                mma16816(accO[2*jj],   pa_l, b0h);
                mma16816(accO[2*jj+1], pa_h, b1h);
                mma16816(accO[2*jj+1], pa_h, b1l);
                mma16816(accO[2*jj+1], pa_l, b1h);
            }
        }
    }

    // ---- one final row-sum reduction, then write ctx as bf16 hi/lo ----
#pragma unroll
    for (int o = 1; o <= 2; o <<= 1) {
        l[0] += __shfl_xor_sync(0xffffffffu, l[0], o);
        l[1] += __shfl_xor_sync(0xffffffffu, l[1], o);
    }
    const float inv0 = 1.f / l[0], inv1 = 1.f / l[1];
#pragma unroll
    for (int j = 0; j < 8; j++) {
        const int col = h * 64 + j * 8 + fc;
        const size_t o0 = ((size_t)b * SEQ + qi0) * HIDDEN + col;
        const size_t o1 = ((size_t)b * SEQ + qi0 + 8) * HIDDEN + col;
        float x0 = accO[j][0] * inv0, x1 = accO[j][1] * inv0;
        float y0 = accO[j][2] * inv1, y1 = accO[j][3] * inv1;
        const uint32_t hx = cvt2bf(x0, x1);
        const uint32_t hy = cvt2bf(y0, y1);
        *(uint32_t*)&g_Ch[o0] = hx;
        *(uint32_t*)&g_Cl[o0] = cvt2bf(x0 - __uint_as_float(hx << 16),
                                       x1 - __uint_as_float(hx & 0xFFFF0000u));
        *(uint32_t*)&g_Ch[o1] = hy;
        *(uint32_t*)&g_Cl[o1] = cvt2bf(y0 - __uint_as_float(hy << 16),
                                       y1 - __uint_as_float(hy & 0xFFFF0000u));
    }
}

// ---------------------------------------------------------------------------
extern "C" void kernel_launch(void* const* d_in, const int* in_sizes, int n_in,
                              void* d_out, int out_size)
{
    const float* X  = (const float*)d_in[0];
    const int*   am = (const int*)d_in[1];
    const float* Wq = (const float*)d_in[2];
    const float* Wk = (const float*)d_in[3];
    const float* Wv = (const float*)d_in[4];
    const float* Wo = (const float*)d_in[5];
    const float* bo = (const float*)d_in[6];
    // d_in[7] = alibi: intentionally unused (computed analytically in-kernel)
    float* out = (float*)d_out;

    cudaFuncSetAttribute(attn_k, cudaFuncAttributeMaxDynamicSharedMemorySize,
                         (int)SMEM_ATTN);
    cudaFuncSetAttribute(gemm_qkv,
                         cudaFuncAttributeMaxDynamicSharedMemorySize, SMEM_QKV);
    cudaFuncSetAttribute(gemm_out,
                         cudaFuncAttributeMaxDynamicSharedMemorySize, SMEM_GEMM);

    // 1) split X / weights to bf16 hi/lo
    conv_split<<<MROWS * HIDDEN / 1024, 256>>>(X);
    dim3 gw(HIDDEN / 32, HIDDEN / 32, 4);
    conv_wT<<<gw, 256>>>(Wq, Wk, Wv, Wo);

    // 2) fused QKV projections (z folded into one CTA; A loaded once)
    dim3 g1(HIDDEN / 128, MROWS / 128);
    gemm_qkv<<<g1, 512, SMEM_QKV>>>();

    // 3) HMMA flash attention
    dim3 g2(SEQ / 64, NHEAD, BATCH);
    attn_k<<<g2, 128, SMEM_ATTN>>>(am);

    // 4) output projection
    dim3 g3(HIDDEN / 128, MROWS / 128);
    gemm_out<<<g3, 512, SMEM_GEMM>>>(bo, out);
}

// round 15
// speedup vs baseline: 1.0063x; 1.0063x over previous
#include <cuda_runtime.h>
#include <cuda_bf16.h>
#include <math.h>
#include <cstdint>

#define BATCH  2
#define SEQ    2048
#define HIDDEN 1024
#define NHEAD  16
#define HD     64
#define MROWS  (BATCH*SEQ)   // 4096

__device__ __forceinline__ float tanha(float x) {
    asm("tanh.approx.f32 %0,%0;" : "+f"(x)); return x;
}
__device__ __forceinline__ uint32_t smem_u32(const void* p) {
    uint32_t a;
    asm("{ .reg .u64 t; cvta.to.shared.u64 t, %1; cvt.u32.u64 %0, t; }"
        : "=r"(a) : "l"(p));
    return a;
}
__device__ __forceinline__ void ldsm4(uint32_t* r, uint32_t addr) {
    asm volatile("ldmatrix.sync.aligned.m8n8.x4.shared.b16 {%0,%1,%2,%3}, [%4];"
                 : "=r"(r[0]), "=r"(r[1]), "=r"(r[2]), "=r"(r[3]) : "r"(addr));
}
__device__ __forceinline__ void mma16816(float* c, const uint32_t* a,
                                         const uint32_t* b) {
    asm volatile(
        "mma.sync.aligned.m16n8k16.row.col.f32.bf16.bf16.f32 "
        "{%0,%1,%2,%3}, {%4,%5,%6,%7}, {%8,%9}, {%0,%1,%2,%3};"
        : "+f"(c[0]), "+f"(c[1]), "+f"(c[2]), "+f"(c[3])
        : "r"(a[0]), "r"(a[1]), "r"(a[2]), "r"(a[3]), "r"(b[0]), "r"(b[1]));
}
__device__ __forceinline__ void cpa16(uint32_t dst, const void* src) {
    asm volatile("cp.async.cg.shared.global [%0], [%1], 16;"
                 :: "r"(dst), "l"(src));
}
#define CP_COMMIT() asm volatile("cp.async.commit_group;" ::: "memory")
#define CP_WAIT0()  asm volatile("cp.async.wait_group 0;" ::: "memory")

// packed split: h = bf16x2(lo=x, hi=y); residuals handled by caller
__device__ __forceinline__ uint32_t cvt2bf(float lo, float hi) {
    uint32_t r;
    asm("cvt.rn.bf16x2.f32 %0,%1,%2;" : "=r"(r) : "f"(hi), "f"(lo));
    return r;
}
// softcap + fixed-shift exp: p = exp(30*tanh((s/8 + ab)/30) - 30)
__device__ __forceinline__ float softcap_p(float s, float ab) {
    float t = fmaf(s, 0.125f, ab);
    float th = tanha(t * (1.f / 30.f));
    return __expf(fmaf(30.f, th, -30.f));
}

// ---- scratch (device globals; ONLY referenced from device code) ------------
__device__ __align__(16) __nv_bfloat16 g_Xh[MROWS*HIDDEN];
__device__ __align__(16) __nv_bfloat16 g_Xl[MROWS*HIDDEN];
__device__ __align__(16) __nv_bfloat16 g_Ch[MROWS*HIDDEN];
__device__ __align__(16) __nv_bfloat16 g_Cl[MROWS*HIDDEN];
__device__ __align__(16) __nv_bfloat16 g_Wh[4*HIDDEN*HIDDEN];  // [z][n][k]
__device__ __align__(16) __nv_bfloat16 g_Wl[4*HIDDEN*HIDDEN];
__device__ __align__(16) __nv_bfloat16 g_Qh[BATCH*NHEAD*SEQ*HD]; // [b,h,s,d]
__device__ __align__(16) __nv_bfloat16 g_Ql[BATCH*NHEAD*SEQ*HD];
__device__ __align__(16) __nv_bfloat16 g_Kh[BATCH*NHEAD*SEQ*HD];
__device__ __align__(16) __nv_bfloat16 g_Kl[BATCH*NHEAD*SEQ*HD];
__device__ __align__(16) __nv_bfloat16 g_Vth[BATCH*NHEAD*HD*SEQ]; // [b,h,d,s]
__device__ __align__(16) __nv_bfloat16 g_Vtl[BATCH*NHEAD*HD*SEQ];

// ---------------------------------------------------------------------------
// Split fp32 X -> bf16 hi/lo.
// ---------------------------------------------------------------------------
__global__ __launch_bounds__(256)
void conv_split(const float* __restrict__ src)
{
    size_t i = ((size_t)blockIdx.x * 256 + threadIdx.x) * 4;
    float4 v = *(const float4*)(src + i);
    __nv_bfloat16 h0 = __float2bfloat16(v.x), h1 = __float2bfloat16(v.y);
    __nv_bfloat16 h2 = __float2bfloat16(v.z), h3 = __float2bfloat16(v.w);
    __nv_bfloat16 l0 = __float2bfloat16(v.x - __bfloat162float(h0));
    __nv_bfloat16 l1 = __float2bfloat16(v.y - __bfloat162float(h1));
    __nv_bfloat16 l2 = __float2bfloat16(v.z - __bfloat162float(h2));
    __nv_bfloat16 l3 = __float2bfloat16(v.w - __bfloat162float(h3));
    __nv_bfloat162* hp = (__nv_bfloat162*)(g_Xh + i);
    __nv_bfloat162* lp = (__nv_bfloat162*)(g_Xl + i);
    hp[0] = __nv_bfloat162(h0, h1); hp[1] = __nv_bfloat162(h2, h3);
    lp[0] = __nv_bfloat162(l0, l1); lp[1] = __nv_bfloat162(l2, l3);
}

// ---------------------------------------------------------------------------
// Transpose + split the 4 weight matrices: W[k][n] fp32 -> Wh/Wl[z][n][k] bf16.
// ---------------------------------------------------------------------------
__global__ __launch_bounds__(256)
void conv_wT(const float* __restrict__ W0, const float* __restrict__ W1,
             const float* __restrict__ W2, const float* __restrict__ W3)
{
    __shared__ float t[32][33];
    const int z = blockIdx.z;
    const float* W = (z == 0) ? W0 : (z == 1) ? W1 : (z == 2) ? W2 : W3;
    __nv_bfloat16* Ho = g_Wh + (size_t)z * HIDDEN * HIDDEN;
    __nv_bfloat16* Lo = g_Wl + (size_t)z * HIDDEN * HIDDEN;
    const int k0 = blockIdx.x * 32, n0 = blockIdx.y * 32;
    const int tx = threadIdx.x & 31, ty = threadIdx.x >> 5;  // 32x8
#pragma unroll
    for (int r = 0; r < 4; r++)
        t[ty + r * 8][tx] = W[(size_t)(k0 + ty + r * 8) * HIDDEN + n0 + tx];
    __syncthreads();
#pragma unroll
    for (int r = 0; r < 4; r++) {
        int nr = ty + r * 8;
        float x = t[tx][nr];
        __nv_bfloat16 h = __float2bfloat16(x);
        Ho[(size_t)(n0 + nr) * HIDDEN + k0 + tx] = h;
        Lo[(size_t)(n0 + nr) * HIDDEN + k0 + tx] =
            __float2bfloat16(x - __bfloat162float(h));
    }
}

// ---------------------------------------------------------------------------
// HMMA GEMM (R12, the 602-us config — reverted from the R13 fusion):
// 512 thr = 16 warps (4m x 4n), warp tile 32x32, CTA tile 128x128, K-chunk 32,
// cp.async 2-stage, one sync per chunk, ldmatrix fragments, 3-pass bf16 split.
// MODE 0: X -> Q/K (split) + V (split, transposed).
// MODE 1: ctx(hi/lo) -> d_out fp32 (+bias).
// ---------------------------------------------------------------------------
#define GLDA 40
#define GTILE_B (128*GLDA*2)
#define GBUF_B  (4*GTILE_B)
#define SMEM_GEMM (2*GBUF_B)

template<int MODE>
__global__ __launch_bounds__(512)
void gemm_mma(const float* __restrict__ bias, float* __restrict__ Cout)
{
    extern __shared__ __align__(16) char gsm[];
    const uint32_t sb = smem_u32(gsm);

    const int tid = threadIdx.x;
    const int wid = tid >> 5, lane = tid & 31;
    const int wm = wid >> 2, wn = wid & 3;           // 4x4 warp grid
    const int bn = blockIdx.x * 128, bm = blockIdx.y * 128;
    const int z = (MODE == 0) ? blockIdx.z : 3;

    const __nv_bfloat16* Ahg = (MODE == 0) ? g_Xh : g_Ch;
    const __nv_bfloat16* Alg = (MODE == 0) ? g_Xl : g_Cl;
    const __nv_bfloat16* Bhg = g_Wh + (size_t)z * HIDDEN * HIDDEN;
    const __nv_bfloat16* Blg = g_Wl + (size_t)z * HIDDEN * HIDDEN;

    const int lr = tid >> 2;        // load row (0..127)
    const int lku = tid & 3;        // 16B k-unit (0..3)

    float acc[2][4][4];
#pragma unroll
    for (int i = 0; i < 2; i++)
#pragma unroll
        for (int j = 0; j < 4; j++)
#pragma unroll
            for (int q = 0; q < 4; q++) acc[i][j][q] = 0.f;

    auto load_chunk = [&](int c) {
        const int k0 = c * 32;
        const uint32_t bb = sb + (c & 1) * GBUF_B;
        const size_t goA = (size_t)(bm + lr) * HIDDEN + k0 + lku * 8;
        const size_t goB = (size_t)(bn + lr) * HIDDEN + k0 + lku * 8;
        const uint32_t so = (lr * GLDA + lku * 8) * 2;
        cpa16(bb + 0 * GTILE_B + so, Ahg + goA);
        cpa16(bb + 1 * GTILE_B + so, Alg + goA);
        cpa16(bb + 2 * GTILE_B + so, Bhg + goB);
        cpa16(bb + 3 * GTILE_B + so, Blg + goB);
    };

    load_chunk(0);
    CP_COMMIT();

    const int lrow = lane & 15;
    const int lcol = (lane >> 4) * 8;

    for (int c = 0; c < 32; c++) {
        CP_WAIT0();
        __syncthreads();   // data(c) arrived AND all warps done reading (c-1)
        if (c + 1 < 32) { load_chunk(c + 1); CP_COMMIT(); }

        const uint32_t bb = sb + (c & 1) * GBUF_B;
#pragma unroll
        for (int kt = 0; kt < 2; kt++) {
            const int kc = kt * 16 + lcol;
            uint32_t ah[2][4], al[2][4];
#pragma unroll
            for (int i = 0; i < 2; i++) {
                const int row = wm * 32 + i * 16 + lrow;
                const uint32_t ao = (row * GLDA + kc) * 2;
                ldsm4(ah[i], bb + 0 * GTILE_B + ao);
                ldsm4(al[i], bb + 1 * GTILE_B + ao);
            }
            uint32_t bh[4][2], bl[4][2];
#pragma unroll
            for (int jj = 0; jj < 2; jj++) {
                const int row = wn * 32 + jj * 16 + lrow;
                const uint32_t bo = (row * GLDA + kc) * 2;
                uint32_t t4[4];
                ldsm4(t4, bb + 2 * GTILE_B + bo);
                bh[2*jj][0]   = t4[0]; bh[2*jj][1]   = t4[2];
                bh[2*jj+1][0] = t4[1]; bh[2*jj+1][1] = t4[3];
                ldsm4(t4, bb + 3 * GTILE_B + bo);
                bl[2*jj][0]   = t4[0]; bl[2*jj][1]   = t4[2];
                bl[2*jj+1][0] = t4[1]; bl[2*jj+1][1] = t4[3];
            }
#pragma unroll
            for (int i = 0; i < 2; i++)
#pragma unroll
                for (int j = 0; j < 4; j++) {
                    mma16816(acc[i][j], ah[i], bh[j]);
                    mma16816(acc[i][j], ah[i], bl[j]);
                    mma16816(acc[i][j], al[i], bh[j]);
                }
        }
    }

    const int g2 = lane >> 2, q2 = (lane & 3) * 2;
#pragma unroll
    for (int i = 0; i < 2; i++) {
        const int row0 = bm + wm * 32 + i * 16 + g2;
#pragma unroll
        for (int j = 0; j < 4; j++) {
            const int col = bn + wn * 32 + j * 8 + q2;
            if (MODE == 0) {
                const int h = col >> 6, d = col & 63;
                if (z < 2) {
                    __nv_bfloat16* Hm = z ? g_Kh : g_Qh;
                    __nv_bfloat16* Lm = z ? g_Kl : g_Ql;
#pragma unroll
                    for (int rr = 0; rr < 2; rr++) {
                        const int row = row0 + rr * 8;
                        const int bb = row >> 11, ss = row & (SEQ - 1);
                        const size_t o =
                            (((size_t)(bb * NHEAD + h) * SEQ) + ss) * HD + d;
                        const float x0 = acc[i][j][rr * 2];
                        const float x1 = acc[i][j][rr * 2 + 1];
                        const uint32_t hh = cvt2bf(x0, x1);
                        *(uint32_t*)&Hm[o] = hh;
                        *(uint32_t*)&Lm[o] = cvt2bf(
                            x0 - __uint_as_float(hh << 16),
                            x1 - __uint_as_float(hh & 0xFFFF0000u));
                    }
                } else {
#pragma unroll
                    for (int rr = 0; rr < 2; rr++) {
                        const int row = row0 + rr * 8;
                        const int bb = row >> 11, ss = row & (SEQ - 1);
                        const size_t base = (size_t)(bb * NHEAD + h) * HD;
#pragma unroll
                        for (int cc = 0; cc < 2; cc++) {
                            const float x = acc[i][j][rr * 2 + cc];
                            __nv_bfloat16 hh = __float2bfloat16(x);
                            const size_t o = (base + d + cc) * SEQ + ss;
                            g_Vth[o] = hh;
                            g_Vtl[o] =
                                __float2bfloat16(x - __bfloat162float(hh));
                        }
                    }
                }
            } else {
                const float2 bb2 = *(const float2*)(bias + col);
                float* p0 = Cout + (size_t)row0 * HIDDEN + col;
                *(float2*)p0 = make_float2(acc[i][j][0] + bb2.x,
                                           acc[i][j][1] + bb2.y);
                float* p1 = Cout + (size_t)(row0 + 8) * HIDDEN + col;
                *(float2*)p1 = make_float2(acc[i][j][2] + bb2.x,
                                           acc[i][j][3] + bb2.y);
            }
        }
    }
}

// ---------------------------------------------------------------------------
// HMMA flash attention v6: occupancy push. Q kept in smem (re-ldsm per kk,
// frees 32 regs), K/V single-buffered (smem 55.5 KB/CTA), reg cap 128 via
// __launch_bounds__(128,4) -> 4 CTAs/SM = 16 warps = 4/SMSP.
// Fixed softcap shift, fused softmax->PV, descending-qt order.
// ---------------------------------------------------------------------------
#define ALD 72
#define ATB (64*ALD*2)            // 9216 B per tile
#define A_QH 0
#define A_QL ATB
#define A_KH (2*ATB)
#define A_KL (3*ATB)
#define A_VH (4*ATB)
#define A_VL (5*ATB)
#define A_MSK (6*ATB)
#define SMEM_ATTN (6*ATB + 256)   // 55552 B

__global__ __launch_bounds__(128, 4)
void attn_k(const int* __restrict__ amask)
{
    extern __shared__ __align__(16) char smb[];
    const uint32_t sb = smem_u32(smb);

    const int qt = gridDim.x - 1 - blockIdx.x;   // big tiles first (LPT)
    const int h = blockIdx.y, b = blockIdx.z;
    const int tid = threadIdx.x;
    const int wid = tid >> 5, lane = tid & 31;
    const int fr = lane >> 2, fc = (lane & 3) * 2;
    const int lrow = lane & 15, lcol = (lane >> 4) * 8;
    const float slope = exp2f(-0.5f * (float)(h + 1));
    const float sl8 = slope * 0.125f;

    const size_t hb = (size_t)(b * NHEAD + h);
    const __nv_bfloat16* Khg0 = g_Kh + hb * SEQ * HD;
    const __nv_bfloat16* Klg0 = g_Kl + hb * SEQ * HD;
    const __nv_bfloat16* Vhg0 = g_Vth + hb * HD * SEQ;
    const __nv_bfloat16* Vlg0 = g_Vtl + hb * HD * SEQ;
    const int* mrow = amask + b * SEQ;

    const int m0 = wid * 16;

    // ---- load Q tiles into persistent smem region ----
    {
        const __nv_bfloat16* Qhg = g_Qh + (hb * SEQ + qt * 64) * HD;
        const __nv_bfloat16* Qlg = g_Ql + (hb * SEQ + qt * 64) * HD;
        __nv_bfloat16* tQh = (__nv_bfloat16*)(smb + A_QH);
        __nv_bfloat16* tQl = (__nv_bfloat16*)(smb + A_QL);
#pragma unroll
        for (int it = 0; it < 4; it++) {
            const int i = tid + it * 128;
            const int row = i >> 3, u = (i & 7) * 8;
            *(uint4*)&tQh[row * ALD + u] = *(const uint4*)(Qhg + row * HD + u);
            *(uint4*)&tQl[row * ALD + u] = *(const uint4*)(Qlg + row * HD + u);
        }
    }

    float l[2] = {0.f, 0.f};
    float accO[8][4];
#pragma unroll
    for (int j = 0; j < 8; j++)
#pragma unroll
        for (int q = 0; q < 4; q++) accO[j][q] = 0.f;

    const int qi0 = qt * 64 + m0 + fr;

    for (int kt = 0; kt <= qt; kt++) {
        __syncthreads();   // prev tile reads done (and Q stores visible, kt=0)
        {
            const __nv_bfloat16* Khg = Khg0 + (size_t)kt * 64 * HD;
            const __nv_bfloat16* Klg = Klg0 + (size_t)kt * 64 * HD;
            const __nv_bfloat16* Vhg = Vhg0 + kt * 64;
            const __nv_bfloat16* Vlg = Vlg0 + kt * 64;
#pragma unroll
            for (int it = 0; it < 4; it++) {
                const int i = tid + it * 128;
                const int row = i >> 3, u = (i & 7) * 8;
                const uint32_t so = (row * ALD + u) * 2;
                cpa16(sb + A_KH + so, Khg + row * HD + u);
                cpa16(sb + A_KL + so, Klg + row * HD + u);
                cpa16(sb + A_VH + so, Vhg + (size_t)row * SEQ + u);
                cpa16(sb + A_VL + so, Vlg + (size_t)row * SEQ + u);
            }
            if (tid < 16) cpa16(sb + A_MSK + tid * 16, mrow + kt * 64 + tid * 4);
        }
        CP_COMMIT();
        CP_WAIT0();
        __syncthreads();   // tile visible to all warps

        const int* padm = (const int*)(smb + A_MSK);

        // ---- S = Q K^T (3-pass); Q re-ldsm'd per kk ----
        float sacc[8][4];
#pragma unroll
        for (int j = 0; j < 8; j++)
#pragma unroll
            for (int q = 0; q < 4; q++) sacc[j][q] = 0.f;

#pragma unroll
        for (int kk = 0; kk < 4; kk++) {
            const uint32_t kc2 = (kk * 16 + lcol) * 2;
            uint32_t qh[4], ql[4];
            const uint32_t ao = (uint32_t)((m0 + lrow) * ALD * 2) + kc2;
            ldsm4(qh, sb + A_QH + ao);
            ldsm4(ql, sb + A_QL + ao);
#pragma unroll
            for (int jj = 0; jj < 4; jj++) {
                const uint32_t bo = (uint32_t)((jj * 16 + lrow) * ALD * 2) + kc2;
                uint32_t th[4], tl[4];
                ldsm4(th, sb + A_KH + bo);
                ldsm4(tl, sb + A_KL + bo);
                uint32_t b0h[2] = { th[0], th[2] }, b1h[2] = { th[1], th[3] };
                uint32_t b0l[2] = { tl[0], tl[2] }, b1l[2] = { tl[1], tl[3] };
                mma16816(sacc[2*jj],   qh, b0h);
                mma16816(sacc[2*jj],   qh, b0l);
                mma16816(sacc[2*jj],   ql, b0h);
                mma16816(sacc[2*jj+1], qh, b1h);
                mma16816(sacc[2*jj+1], qh, b1l);
                mma16816(sacc[2*jj+1], ql, b1h);
            }
        }

        // ---- fused softcap+fixed-shift softmax -> PV per k-chunk ----
        const bool diag = (kt == qt);
        const int pv0 = padm[2 * lane], pv1 = padm[2 * lane + 1];
        const bool allok = __all_sync(0xffffffffu, pv0 && pv1);
        const bool slow = diag || !allok;
        const float aK = sl8 * (float)(64 * (kt - qt) + fc - m0 - fr);

#pragma unroll
        for (int kk = 0; kk < 4; kk++) {
            uint32_t pa_h[4], pa_l[4];
#pragma unroll
            for (int jj2 = 0; jj2 < 2; jj2++) {
                const int j = 2 * kk + jj2;
                const float abj = fmaf(sl8, (float)(8 * j), aK);
                float p00 = softcap_p(sacc[j][0], abj);
                float p01 = softcap_p(sacc[j][1], abj + sl8);
                float p10 = softcap_p(sacc[j][2], abj - 8.f * sl8);
                float p11 = softcap_p(sacc[j][3], abj - 7.f * sl8);
                if (slow) {
                    const int kc0 = kt * 64 + j * 8 + fc;
                    const int pm0 = padm[j * 8 + fc];
                    const int pm1 = padm[j * 8 + fc + 1];
                    const int qiA = qi0, qiB = qi0 + 8;
                    if (pm0 == 0 || (diag && kc0     > qiA)) p00 = 0.f;
                    if (pm1 == 0 || (diag && kc0 + 1 > qiA)) p01 = 0.f;
                    if (pm0 == 0 || (diag && kc0     > qiB)) p10 = 0.f;
                    if (pm1 == 0 || (diag && kc0 + 1 > qiB)) p11 = 0.f;
                }
                l[0] += p00 + p01;
                l[1] += p10 + p11;
                const uint32_t h0 = cvt2bf(p00, p01);
                const uint32_t h1 = cvt2bf(p10, p11);
                pa_h[jj2 * 2]     = h0;
                pa_h[jj2 * 2 + 1] = h1;
                pa_l[jj2 * 2]     = cvt2bf(
                    p00 - __uint_as_float(h0 << 16),
                    p01 - __uint_as_float(h0 & 0xFFFF0000u));
                pa_l[jj2 * 2 + 1] = cvt2bf(
                    p10 - __uint_as_float(h1 << 16),
                    p11 - __uint_as_float(h1 & 0xFFFF0000u));
            }
            const uint32_t kc2 = (kk * 16 + lcol) * 2;
#pragma unroll
            for (int jj = 0; jj < 4; jj++) {
                const uint32_t bo = (uint32_t)((jj * 16 + lrow) * ALD * 2) + kc2;
                uint32_t th[4], tl[4];
                ldsm4(th, sb + A_VH + bo);
                ldsm4(tl, sb + A_VL + bo);
                uint32_t b0h[2] = { th[0], th[2] }, b1h[2] = { th[1], th[3] };
                uint32_t b0l[2] = { tl[0], tl[2] }, b1l[2] = { tl[1], tl[3] };
                mma16816(accO[2*jj],   pa_h, b0h);
                mma16816(accO[2*jj],   pa_h, b0l);
                mma16816(accO[2*jj],   pa_l, b0h);
                mma16816(accO[2*jj+1], pa_h, b1h);
                mma16816(accO[2*jj+1], pa_h, b1l);
                mma16816(accO[2*jj+1], pa_l, b1h);
            }
        }
    }

    // ---- one final row-sum reduction, then write ctx as bf16 hi/lo ----
#pragma unroll
    for (int o = 1; o <= 2; o <<= 1) {
        l[0] += __shfl_xor_sync(0xffffffffu, l[0], o);
        l[1] += __shfl_xor_sync(0xffffffffu, l[1], o);
    }
    const float inv0 = 1.f / l[0], inv1 = 1.f / l[1];
#pragma unroll
    for (int j = 0; j < 8; j++) {
        const int col = h * 64 + j * 8 + fc;
        const size_t o0 = ((size_t)b * SEQ + qi0) * HIDDEN + col;
        const size_t o1 = ((size_t)b * SEQ + qi0 + 8) * HIDDEN + col;
        float x0 = accO[j][0] * inv0, x1 = accO[j][1] * inv0;
        float y0 = accO[j][2] * inv1, y1 = accO[j][3] * inv1;
        const uint32_t hx = cvt2bf(x0, x1);
        const uint32_t hy = cvt2bf(y0, y1);
        *(uint32_t*)&g_Ch[o0] = hx;
        *(uint32_t*)&g_Cl[o0] = cvt2bf(x0 - __uint_as_float(hx << 16),
                                       x1 - __uint_as_float(hx & 0xFFFF0000u));
        *(uint32_t*)&g_Ch[o1] = hy;
        *(uint32_t*)&g_Cl[o1] = cvt2bf(y0 - __uint_as_float(hy << 16),
                                       y1 - __uint_as_float(hy & 0xFFFF0000u));
    }
}

// ---------------------------------------------------------------------------
extern "C" void kernel_launch(void* const* d_in, const int* in_sizes, int n_in,
                              void* d_out, int out_size)
{
    const float* X  = (const float*)d_in[0];
    const int*   am = (const int*)d_in[1];
    const float* Wq = (const float*)d_in[2];
    const float* Wk = (const float*)d_in[3];
    const float* Wv = (const float*)d_in[4];
    const float* Wo = (const float*)d_in[5];
    const float* bo = (const float*)d_in[6];
    // d_in[7] = alibi: intentionally unused (computed analytically in-kernel)
    float* out = (float*)d_out;

    cudaFuncSetAttribute(attn_k, cudaFuncAttributeMaxDynamicSharedMemorySize,
                         (int)SMEM_ATTN);
    cudaFuncSetAttribute(gemm_mma<0>,
                         cudaFuncAttributeMaxDynamicSharedMemorySize, SMEM_GEMM);
    cudaFuncSetAttribute(gemm_mma<1>,
                         cudaFuncAttributeMaxDynamicSharedMemorySize, SMEM_GEMM);

    // 1) split X / weights to bf16 hi/lo
    conv_split<<<MROWS * HIDDEN / 1024, 256>>>(X);
    dim3 gw(HIDDEN / 32, HIDDEN / 32, 4);
    conv_wT<<<gw, 256>>>(Wq, Wk, Wv, Wo);

    // 2) fused QKV projections -> pre-split bf16 Q/K + transposed V
    dim3 g1(HIDDEN / 128, MROWS / 128, 3);
    gemm_mma<0><<<g1, 512, SMEM_GEMM>>>(nullptr, nullptr);

    // 3) HMMA flash attention (4 CTAs/SM)
    dim3 g2(SEQ / 64, NHEAD, BATCH);
    attn_k<<<g2, 128, SMEM_ATTN>>>(am);

    // 4) output projection
    dim3 g3(HIDDEN / 128, MROWS / 128, 1);
    gemm_mma<1><<<g3, 512, SMEM_GEMM>>>(bo, out);
}